// round 6
// baseline (speedup 1.0000x reference)
#include <cuda_runtime.h>
#include <cstdint>

// Problem constants
#define B_    32
#define CIN   128
#define H_    56
#define HW    3136          // 56*56
#define COUT  256
#define KTOT  1152          // CIN*9
#define R_    16
#define KERN_PER_B (COUT*KTOT)      // 294912

// Scratch (static device arrays; no runtime allocation)
__device__ float g_gap[B_ * CIN];
__device__ float g_routing[B_ * 4];
// A (mixed kernels) u8 digit planes: a = (a1*256+a2)/2^16, layout [b][m][k'], k'=r*128+ci
__device__ __align__(16) unsigned char g_A1[(size_t)B_ * COUT * KTOT];
__device__ __align__(16) unsigned char g_A2[(size_t)B_ * COUT * KTOT];
// B (im2col of x) s8 digit planes: b = (b1*256+b2)/2^12, layout [b][n][k']
__device__ __align__(16) signed char g_B1[(size_t)B_ * HW * KTOT];
__device__ __align__(16) signed char g_B2[(size_t)B_ * HW * KTOT];

// ---------------------------------------------------------------------------
// helpers
// ---------------------------------------------------------------------------
__device__ __forceinline__ uint32_t smem_u32(const void* p) {
    uint32_t a;
    asm("{ .reg .u64 t; cvta.to.shared.u64 t, %1; cvt.u32.u64 %0, t; }"
        : "=r"(a) : "l"(p));
    return a;
}
__device__ __forceinline__ void ldmx4(uint32_t* r, uint32_t addr) {
    asm volatile("ldmatrix.sync.aligned.m8n8.x4.shared.b16 {%0,%1,%2,%3}, [%4];"
                 : "=r"(r[0]), "=r"(r[1]), "=r"(r[2]), "=r"(r[3]) : "r"(addr));
}
// D(s32) += A(u8) * B(s8), m16n8k32
__device__ __forceinline__ void imma(int* d, const uint32_t* a, const uint32_t* b) {
    asm volatile(
        "mma.sync.aligned.m16n8k32.row.col.s32.u8.s8.s32 "
        "{%0,%1,%2,%3},{%4,%5,%6,%7},{%8,%9},{%0,%1,%2,%3};"
        : "+r"(d[0]), "+r"(d[1]), "+r"(d[2]), "+r"(d[3])
        : "r"(a[0]), "r"(a[1]), "r"(a[2]), "r"(a[3]), "r"(b[0]), "r"(b[1]));
}
__device__ __forceinline__ void cp16(uint32_t dst, const void* src) {
    asm volatile("cp.async.cg.shared.global [%0], [%1], 16;" :: "r"(dst), "l"(src));
}
__device__ __forceinline__ void cp_commit() {
    asm volatile("cp.async.commit_group;" ::: "memory");
}

// ---------------------------------------------------------------------------
// 1) Global average pool
// ---------------------------------------------------------------------------
__global__ void gap_kernel(const float* __restrict__ x) {
    const int idx = blockIdx.x;
    const float* p = x + (size_t)idx * HW;
    float s = 0.f;
    for (int i = threadIdx.x; i < HW; i += 256) s += p[i];
    #pragma unroll
    for (int o = 16; o > 0; o >>= 1) s += __shfl_xor_sync(0xffffffffu, s, o);
    __shared__ float sm[8];
    if ((threadIdx.x & 31) == 0) sm[threadIdx.x >> 5] = s;
    __syncthreads();
    if (threadIdx.x < 8) {
        s = sm[threadIdx.x];
        s += __shfl_xor_sync(0xffu, s, 4);
        s += __shfl_xor_sync(0xffu, s, 2);
        s += __shfl_xor_sync(0xffu, s, 1);
        if (threadIdx.x == 0) g_gap[idx] = s * (1.0f / 3136.0f);
    }
}

// ---------------------------------------------------------------------------
// 2) Router MLP + softmax(logits/30)
// ---------------------------------------------------------------------------
__global__ void routing_kernel(const float* __restrict__ w1, const float* __restrict__ b1,
                               const float* __restrict__ w2, const float* __restrict__ b2) {
    const int b = threadIdx.x;
    if (b >= B_) return;
    float h[R_];
    #pragma unroll
    for (int r = 0; r < R_; r++) {
        float s = b1[r];
        for (int c = 0; c < CIN; c++) s += g_gap[b * CIN + c] * w1[r * CIN + c];
        h[r] = fmaxf(s, 0.f);
    }
    float lg[4];
    float mx = -1e30f;
    #pragma unroll
    for (int e = 0; e < 4; e++) {
        float s = b2[e];
        #pragma unroll
        for (int r = 0; r < R_; r++) s += h[r] * w2[e * R_ + r];
        lg[e] = s * (1.0f / 30.0f);
        mx = fmaxf(mx, lg[e]);
    }
    float den = 0.f;
    #pragma unroll
    for (int e = 0; e < 4; e++) { lg[e] = __expf(lg[e] - mx); den += lg[e]; }
    const float inv = 1.0f / den;
    #pragma unroll
    for (int e = 0; e < 4; e++) g_routing[b * 4 + e] = lg[e] * inv;
}

// ---------------------------------------------------------------------------
// 3) Mix + quantize A: a in [0,1) -> u16 fixed -> u8 digit planes, k'=r*128+ci
// ---------------------------------------------------------------------------
__global__ void aquant_kernel(const float* __restrict__ convs) {
    const int m = blockIdx.x;
    const int b = blockIdx.y;
    const float r0 = g_routing[b * 4 + 0];
    const float r1 = g_routing[b * 4 + 1];
    const float r2 = g_routing[b * 4 + 2];
    const float r3 = g_routing[b * 4 + 3];
    for (int p = threadIdx.x; p < KTOT / 4; p += 128) {
        const int k0 = p * 4;
        const int r  = k0 >> 7;
        const int ci0 = k0 & 127;
        uint32_t hi = 0, lo = 0;
        #pragma unroll
        for (int j = 0; j < 4; j++) {
            const int idx = m * KTOT + (ci0 + j) * 9 + r;
            float v = r0 * convs[idx] + r1 * convs[idx + KERN_PER_B]
                    + r2 * convs[idx + 2 * KERN_PER_B] + r3 * convs[idx + 3 * KERN_PER_B];
            int A16 = (int)fminf(v * 65536.f + 0.5f, 65535.f);
            if (A16 < 0) A16 = 0;
            hi |= (uint32_t)(A16 >> 8) << (j * 8);
            lo |= (uint32_t)(A16 & 255) << (j * 8);
        }
        const size_t off = ((size_t)(b * COUT + m) * KTOT + k0) >> 2;
        ((uint32_t*)g_A1)[off] = hi;
        ((uint32_t*)g_A2)[off] = lo;
    }
}

// ---------------------------------------------------------------------------
// 4) im2col + quantize B: b = x*4096 (s16) -> s8 digit planes, layout [b][n][k']
//    One block per (b, oh); smem holds 3 input rows x 128 ci x 56 w.
// ---------------------------------------------------------------------------
#define BQ_SMEM (3 * 128 * 56 * 4)
__global__ void bquant_kernel(const float* __restrict__ x) {
    extern __shared__ float sm[];        // [rr 0..2][ci 0..127][w 0..55]
    const int oh = blockIdx.x;
    const int b  = blockIdx.y;
    for (int i = threadIdx.x; i < 3 * 128 * 56; i += 256) {
        const int rr  = i / (128 * 56);
        const int rem = i - rr * 128 * 56;
        const int ci  = rem / 56;
        const int w   = rem - ci * 56;
        const int ih  = oh + rr - 1;
        sm[i] = ((unsigned)ih < (unsigned)H_)
                    ? x[((size_t)(b * CIN + ci) * H_ + ih) * H_ + w] : 0.f;
    }
    __syncthreads();
    for (int idx = threadIdx.x; idx < 56 * 72; idx += 256) {
        const int ow = idx / 72;
        const int ch = idx - ow * 72;            // 16-k' chunk
        const int r   = ch >> 3;                 // 0..8
        const int ci0 = (ch & 7) * 16;
        const int rr  = r / 3;                   // smem row index
        const int dw  = r - rr * 3 - 1;
        const int iw  = ow + dw;
        const bool vw = (unsigned)iw < (unsigned)H_;
        uint32_t h[4] = {0, 0, 0, 0}, l[4] = {0, 0, 0, 0};
        #pragma unroll
        for (int j = 0; j < 16; j++) {
            float v = vw ? sm[(rr * 128 + ci0 + j) * 56 + iw] : 0.f;
            int t = __float2int_rn(v * 4096.f);
            int b2 = ((t + 128) & 255) - 128;
            int b1 = (t - b2) >> 8;
            h[j >> 2] |= (uint32_t)(b1 & 255) << ((j & 3) * 8);
            l[j >> 2] |= (uint32_t)(b2 & 255) << ((j & 3) * 8);
        }
        const size_t off = ((size_t)b * HW + oh * 56 + ow) * KTOT + ch * 16;
        *(uint4*)(g_B1 + off) = make_uint4(h[0], h[1], h[2], h[3]);
        *(uint4*)(g_B2 + off) = make_uint4(l[0], l[1], l[2], l[3]);
    }
}

// ---------------------------------------------------------------------------
// 5) Per-sample GEMM on int8 mma.sync, 3-stage cp.async ring.
//    CTA tile 128m x 64n, BK=32 (36 stages), 8 warps (4m x 2n) -> warp 32m x 32n.
//    Stage smem (12 KB): A1[c][m][16B] 4K | A2 4K | B1[c][n][16B] 2K | B2 2K
//    out = acc1 * 2^-12 + acc23 * 2^-20
// ---------------------------------------------------------------------------
#define STG   12288
#define SM_TOTAL (3 * STG)

__global__ void __launch_bounds__(256, 2)
conv_i8(float* __restrict__ out) {
    extern __shared__ __align__(128) char smem[];
    const uint32_t sb = smem_u32(smem);

    const int tid  = threadIdx.x;
    const int wid  = tid >> 5;
    const int lane = tid & 31;
    const int wm   = wid & 3;          // 4 warps along m
    const int wn   = wid >> 2;         // 2 warps along n

    const int b  = blockIdx.z;
    const int m0 = blockIdx.y * 128;
    const int n0 = blockIdx.x * 64;    // 49*64 = 3136 exactly

    const unsigned char* A1 = g_A1 + (size_t)(b * COUT + m0) * KTOT;
    const unsigned char* A2 = g_A2 + (size_t)(b * COUT + m0) * KTOT;
    const signed char*   B1 = g_B1 + ((size_t)b * HW + n0) * KTOT;
    const signed char*   B2 = g_B2 + ((size_t)b * HW + n0) * KTOT;

    int acc1[2][4][4], acc23[2][4][4];
    #pragma unroll
    for (int mi = 0; mi < 2; mi++)
        #pragma unroll
        for (int nj = 0; nj < 4; nj++)
            #pragma unroll
            for (int q = 0; q < 4; q++) { acc1[mi][nj][q] = 0; acc23[mi][nj][q] = 0; }

    // per-thread load roles (3 cp16 per thread per stage)
    const int am = tid >> 1, ac = tid & 1;                 // A: m row, chunk
    const int bpl = tid >> 7, bn = (tid >> 1) & 63, bc = tid & 1;  // B: plane, n, chunk
    auto load_stage = [&](int s, int buf) {
        const uint32_t base = sb + buf * STG;
        const size_t koff = (size_t)s * 32;
        cp16(base + ac * 2048 + am * 16,        A1 + (size_t)am * KTOT + koff + ac * 16);
        cp16(base + 4096 + ac * 2048 + am * 16, A2 + (size_t)am * KTOT + koff + ac * 16);
        const signed char* bs = (bpl ? B2 : B1) + (size_t)bn * KTOT + koff + bc * 16;
        cp16(base + 8192 + bpl * 2048 + bc * 1024 + bn * 16, bs);
        cp_commit();
    };

    load_stage(0, 0);
    load_stage(1, 1);

    // ldmatrix thread addressing
    const int arow = wm * 32 + (lane & 15);
    const uint32_t ach = (uint32_t)(lane >> 4) * 2048;
    const int nrow = wn * 32 + ((lane >> 4) << 3) + (lane & 7);
    const uint32_t bch = (uint32_t)((lane >> 3) & 1) * 1024;

    for (int s = 0; s < 36; s++) {
        const int buf = s % 3;
        if (s < 35) asm volatile("cp.async.wait_group 1;" ::: "memory");
        else        asm volatile("cp.async.wait_group 0;" ::: "memory");
        __syncthreads();
        if (s + 2 < 36) load_stage(s + 2, (s + 2) % 3);

        const uint32_t base = sb + buf * STG;
        uint32_t aH[2][4], aL[2][4], bH[2][4], bL[2][4];
        ldmx4(aH[0], base + ach + arow * 16);
        ldmx4(aH[1], base + ach + (arow + 16) * 16);
        ldmx4(aL[0], base + 4096 + ach + arow * 16);
        ldmx4(aL[1], base + 4096 + ach + (arow + 16) * 16);
        ldmx4(bH[0], base + 8192 + bch + nrow * 16);
        ldmx4(bH[1], base + 8192 + bch + (nrow + 16) * 16);
        ldmx4(bL[0], base + 10240 + bch + nrow * 16);
        ldmx4(bL[1], base + 10240 + bch + (nrow + 16) * 16);

        #pragma unroll
        for (int mi = 0; mi < 2; mi++)
            #pragma unroll
            for (int nj = 0; nj < 4; nj++) {
                const int g = nj >> 1, hh = (nj & 1) * 2;
                imma(acc1[mi][nj],  aH[mi], &bH[g][hh]);
                imma(acc23[mi][nj], aH[mi], &bL[g][hh]);
                imma(acc23[mi][nj], aL[mi], &bH[g][hh]);
            }
    }

    // ---- epilogue ----
    const float s1 = 1.f / 4096.f, s2 = 1.f / 1048576.f;
    #pragma unroll
    for (int mi = 0; mi < 2; mi++) {
        const int m = m0 + wm * 32 + mi * 16 + (lane >> 2);
        #pragma unroll
        for (int nj = 0; nj < 4; nj++) {
            const int nn = n0 + wn * 32 + nj * 8 + (lane & 3) * 2;
            float* o = out + (size_t)(b * COUT + m) * HW + nn;
            *(float2*)o = make_float2(
                (float)acc1[mi][nj][0] * s1 + (float)acc23[mi][nj][0] * s2,
                (float)acc1[mi][nj][1] * s1 + (float)acc23[mi][nj][1] * s2);
            *(float2*)(o + 8 * HW) = make_float2(
                (float)acc1[mi][nj][2] * s1 + (float)acc23[mi][nj][2] * s2,
                (float)acc1[mi][nj][3] * s1 + (float)acc23[mi][nj][3] * s2);
        }
    }
}

// ---------------------------------------------------------------------------
extern "C" void kernel_launch(void* const* d_in, const int* in_sizes, int n_in,
                              void* d_out, int out_size) {
    const float* x     = (const float*)d_in[0];
    const float* convs = (const float*)d_in[1];
    const float* w1    = (const float*)d_in[2];
    const float* b1    = (const float*)d_in[3];
    const float* w2    = (const float*)d_in[4];
    const float* b2    = (const float*)d_in[5];
    float* out = (float*)d_out;

    cudaFuncSetAttribute(bquant_kernel, cudaFuncAttributeMaxDynamicSharedMemorySize, BQ_SMEM);

    gap_kernel<<<B_ * CIN, 256>>>(x);
    routing_kernel<<<1, 32>>>(w1, b1, w2, b2);
    aquant_kernel<<<dim3(COUT, B_), 128>>>(convs);
    bquant_kernel<<<dim3(H_, B_), 256, BQ_SMEM>>>(x);
    conv_i8<<<dim3(HW / 64, COUT / 128, B_), 256, SM_TOTAL>>>(out);
}

// round 7
// speedup vs baseline: 3.5022x; 3.5022x over previous
#include <cuda_runtime.h>
#include <cuda_fp16.h>
#include <cstdint>

// Problem constants
#define B_    32
#define CIN   128
#define H_    56
#define HW    3136          // 56*56
#define COUT  256
#define KTOT  1152          // CIN*9
#define R_    16
#define KERN_PER_B (COUT*KTOT)      // 294912

// Scratch (static device arrays; no runtime allocation)
__device__ float g_gap[B_ * CIN];
__device__ float g_routing[B_ * 4];
// Mixed conv kernels, k' = r*128+ci ordering, fp16 hi/lo split: [b][m][k']
__device__ __half g_Ah[(size_t)B_ * COUT * KTOT + 64];
__device__ __half g_Al[(size_t)B_ * COUT * KTOT + 64];
// 9 shifted zero-padded fp16 copies of x: [r][b][ci][n]
#define XS_ELEMS ((size_t)9 * B_ * CIN * HW)
__device__ __half g_Xh[XS_ELEMS + 8192];

// ---------------------------------------------------------------------------
// helpers
// ---------------------------------------------------------------------------
__device__ __forceinline__ uint32_t smem_u32(const void* p) {
    uint32_t a;
    asm("{ .reg .u64 t; cvta.to.shared.u64 t, %1; cvt.u32.u64 %0, t; }"
        : "=r"(a) : "l"(p));
    return a;
}
__device__ __forceinline__ void ldmx4(uint32_t* r, uint32_t addr) {
    asm volatile("ldmatrix.sync.aligned.m8n8.x4.shared.b16 {%0,%1,%2,%3}, [%4];"
                 : "=r"(r[0]), "=r"(r[1]), "=r"(r[2]), "=r"(r[3]) : "r"(addr));
}
__device__ __forceinline__ void ldmx4t(uint32_t* r, uint32_t addr) {
    asm volatile("ldmatrix.sync.aligned.m8n8.x4.trans.shared.b16 {%0,%1,%2,%3}, [%4];"
                 : "=r"(r[0]), "=r"(r[1]), "=r"(r[2]), "=r"(r[3]) : "r"(addr));
}
__device__ __forceinline__ void mma_f16(float* d, const uint32_t* a, const uint32_t* b) {
    asm volatile(
        "mma.sync.aligned.m16n8k16.row.col.f32.f16.f16.f32 "
        "{%0,%1,%2,%3},{%4,%5,%6,%7},{%8,%9},{%0,%1,%2,%3};"
        : "+f"(d[0]), "+f"(d[1]), "+f"(d[2]), "+f"(d[3])
        : "r"(a[0]), "r"(a[1]), "r"(a[2]), "r"(a[3]), "r"(b[0]), "r"(b[1]));
}
__device__ __forceinline__ void cp16(uint32_t dst, const void* src) {
    asm volatile("cp.async.cg.shared.global [%0], [%1], 16;" :: "r"(dst), "l"(src));
}
__device__ __forceinline__ void cp_commit() {
    asm volatile("cp.async.commit_group;" ::: "memory");
}
__device__ __forceinline__ void split_hl(float v, __half& h, __half& l) {
    h = __float2half_rn(v);
    l = __float2half_rn(v - __half2float(h));
}
__device__ __forceinline__ uint32_t pack_h2(__half a, __half b) {
    __half2 t = __halves2half2(a, b);
    return *reinterpret_cast<uint32_t*>(&t);
}

// ---------------------------------------------------------------------------
// 1) Global average pool
// ---------------------------------------------------------------------------
__global__ void gap_kernel(const float* __restrict__ x) {
    const int idx = blockIdx.x;
    const float* p = x + (size_t)idx * HW;
    float s = 0.f;
    for (int i = threadIdx.x; i < HW; i += 256) s += p[i];
    #pragma unroll
    for (int o = 16; o > 0; o >>= 1) s += __shfl_xor_sync(0xffffffffu, s, o);
    __shared__ float sm[8];
    if ((threadIdx.x & 31) == 0) sm[threadIdx.x >> 5] = s;
    __syncthreads();
    if (threadIdx.x < 8) {
        s = sm[threadIdx.x];
        s += __shfl_xor_sync(0xffu, s, 4);
        s += __shfl_xor_sync(0xffu, s, 2);
        s += __shfl_xor_sync(0xffu, s, 1);
        if (threadIdx.x == 0) g_gap[idx] = s * (1.0f / 3136.0f);
    }
}

// ---------------------------------------------------------------------------
// 2) Router MLP + softmax(logits/30)
// ---------------------------------------------------------------------------
__global__ void routing_kernel(const float* __restrict__ w1, const float* __restrict__ b1,
                               const float* __restrict__ w2, const float* __restrict__ b2) {
    const int b = threadIdx.x;
    if (b >= B_) return;
    float h[R_];
    #pragma unroll
    for (int r = 0; r < R_; r++) {
        float s = b1[r];
        for (int c = 0; c < CIN; c++) s += g_gap[b * CIN + c] * w1[r * CIN + c];
        h[r] = fmaxf(s, 0.f);
    }
    float lg[4];
    float mx = -1e30f;
    #pragma unroll
    for (int e = 0; e < 4; e++) {
        float s = b2[e];
        #pragma unroll
        for (int r = 0; r < R_; r++) s += h[r] * w2[e * R_ + r];
        lg[e] = s * (1.0f / 30.0f);
        mx = fmaxf(mx, lg[e]);
    }
    float den = 0.f;
    #pragma unroll
    for (int e = 0; e < 4; e++) { lg[e] = __expf(lg[e] - mx); den += lg[e]; }
    const float inv = 1.0f / den;
    #pragma unroll
    for (int e = 0; e < 4; e++) g_routing[b * 4 + e] = lg[e] * inv;
}

// ---------------------------------------------------------------------------
// 3) Shift + pad x into 9 fp16 copies: g_Xh[r][b][ci][n]
// ---------------------------------------------------------------------------
__global__ void shift_kernel(const float* __restrict__ x) {
    __shared__ float plane[HW];
    const int bc = blockIdx.x;               // b*CIN + ci
    const float* src = x + (size_t)bc * HW;
    for (int i = threadIdx.x; i < HW; i += 256) plane[i] = src[i];
    __syncthreads();
    const int b = bc >> 7, ci = bc & 127;
    for (int p = threadIdx.x; p < HW / 2; p += 256) {
        const int n0 = 2 * p;
        const int oh = n0 / H_;
        const int ow = n0 - oh * H_;         // even; ow+1 <= 55 (same row)
        #pragma unroll
        for (int r = 0; r < 9; r++) {
            const int dh = r / 3 - 1, dw = r % 3 - 1;
            const int ih = oh + dh;
            float v0 = 0.f, v1 = 0.f;
            if ((unsigned)ih < (unsigned)H_) {
                const int iw0 = ow + dw;
                if ((unsigned)iw0 < (unsigned)H_) v0 = plane[ih * H_ + iw0];
                const int iw1 = iw0 + 1;
                if ((unsigned)iw1 < (unsigned)H_) v1 = plane[ih * H_ + iw1];
            }
            const size_t off = ((size_t)(r * B_ + b) * CIN + ci) * (HW / 2) + p;
            ((uint32_t*)g_Xh)[off] = pack_h2(__float2half_rn(v0), __float2half_rn(v1));
        }
    }
}

// ---------------------------------------------------------------------------
// 4) Mix expert kernels -> g_A[b][m][k'] with k' = r*128+ci, fp16 hi/lo
// ---------------------------------------------------------------------------
__global__ void mix_kernel(const float* __restrict__ convs) {
    const int m = blockIdx.x;
    const int b = blockIdx.y;
    const float r0 = g_routing[b * 4 + 0];
    const float r1 = g_routing[b * 4 + 1];
    const float r2 = g_routing[b * 4 + 2];
    const float r3 = g_routing[b * 4 + 3];
    for (int p = threadIdx.x; p < KTOT / 2; p += 128) {   // p -> k' pair (2*p, 2*p+1)
        const int r = p >> 6;
        const int ci = (p & 63) * 2;
        const int base = m * KTOT + ci * 9 + r;
        const float* c0 = convs + base;
        float v0 = r0 * c0[0] + r1 * c0[KERN_PER_B] + r2 * c0[2 * KERN_PER_B] + r3 * c0[3 * KERN_PER_B];
        const float* c1 = convs + base + 9;
        float v1 = r0 * c1[0] + r1 * c1[KERN_PER_B] + r2 * c1[2 * KERN_PER_B] + r3 * c1[3 * KERN_PER_B];
        __half h0, l0, h1, l1;
        split_hl(v0, h0, l0);
        split_hl(v1, h1, l1);
        const size_t off = (size_t)(b * COUT + m) * (KTOT / 2) + p;
        ((uint32_t*)g_Ah)[off] = pack_h2(h0, h1);
        ((uint32_t*)g_Al)[off] = pack_h2(l0, l1);
    }
}

// ---------------------------------------------------------------------------
// 5) Per-sample GEMM on mma.sync (fp16 2-pass: ah*bh + al*bh), cp.async DB.
//    CTA tile 128m x 128n, BK=32 (36 stages), 8 warps -> warp tile 64m x 32n.
//    smem: A[2][128 rows][128B: hi 4ch | lo 4ch, XOR swizzle]
//          B[2][32 krows x 256B, XOR swizzle]
// ---------------------------------------------------------------------------
#define STG    24576                 // A 16K + B 8K per stage
#define SM_A(buf)  ((buf) * STG)
#define SM_B(buf)  ((buf) * STG + 16384)
#define SM_TOTAL   (2 * STG)

__global__ void __launch_bounds__(256, 2)
conv_mma(float* __restrict__ out) {
    extern __shared__ __align__(128) char smem[];
    const uint32_t sb = smem_u32(smem);

    const int tid  = threadIdx.x;
    const int wid  = tid >> 5;
    const int lane = tid & 31;
    const int wm   = wid & 1;          // 2 warps along m
    const int wn   = wid >> 1;         // 4 warps along n

    const int b  = blockIdx.z;
    const int m0 = blockIdx.y * 128;
    const int n0 = blockIdx.x * 128;

    float acc[4][4][4];
    #pragma unroll
    for (int i = 0; i < 4; i++)
        #pragma unroll
        for (int j = 0; j < 4; j++)
            #pragma unroll
            for (int q = 0; q < 4; q++) acc[i][j][q] = 0.f;

    // ---- stage loader (A: 1024 cp16, B: 512 cp16 across 256 threads) ----
    auto load_stage = [&](int s, int buf) {
        const int r   = s >> 2;
        const int ci0 = (s & 3) * 32;
        // A: row m 0..127, chunk c 0..7 (c<4 hi, else lo)
        #pragma unroll
        for (int q = 0; q < 4; q++) {
            const int id  = q * 256 + tid;
            const int row = id >> 3;
            const int c   = id & 7;
            const __half* src =
                (c < 4 ? g_Ah : g_Al) + (size_t)(b * COUT + m0 + row) * KTOT + s * 32 + (c & 3) * 8;
            cp16(sb + SM_A(buf) + row * 128 + ((c ^ (row & 7)) * 16), src);
        }
        // B: krow 0..31, chunk c 0..15 (single hi plane)
        #pragma unroll
        for (int q = 0; q < 2; q++) {
            const int id = q * 256 + tid;
            const int kr = id >> 4;
            const int c  = id & 15;
            const __half* src =
                g_Xh + (size_t)((r * B_ + b) * CIN + ci0 + kr) * HW + n0 + c * 8;
            cp16(sb + SM_B(buf) + kr * 256 + ((c ^ (kr & 7)) * 16), src);
        }
        cp_commit();
    };

    load_stage(0, 0);

    for (int s = 0; s < 36; s++) {
        const int buf = s & 1;
        if (s + 1 < 36) {
            load_stage(s + 1, buf ^ 1);
            asm volatile("cp.async.wait_group 1;" ::: "memory");
        } else {
            asm volatile("cp.async.wait_group 0;" ::: "memory");
        }
        __syncthreads();

        #pragma unroll
        for (int ks = 0; ks < 2; ks++) {
            // ---- A hi fragments ----
            uint32_t ah[4][4];
            #pragma unroll
            for (int mi = 0; mi < 4; mi++) {
                const int row = wm * 64 + mi * 16 + (lane & 15);
                const int cl  = ks * 2 + (lane >> 4);
                ldmx4(ah[mi], sb + SM_A(buf) + row * 128 + ((cl ^ (row & 7)) * 16));
            }
            // ---- B fragments (ldmatrix.trans from k-major, single plane) ----
            uint32_t bh[4][2];
            #pragma unroll
            for (int ni = 0; ni < 2; ni++) {
                const int mat = lane >> 3, j = lane & 7;
                const int kr  = ks * 16 + (mat & 1) * 8 + j;
                const int nc  = wn * 4 + ni * 2 + (mat >> 1);
                uint32_t t[4];
                ldmx4t(t, sb + SM_B(buf) + kr * 256 + ((nc ^ (kr & 7)) * 16));
                bh[ni * 2 + 0][0] = t[0]; bh[ni * 2 + 0][1] = t[1];
                bh[ni * 2 + 1][0] = t[2]; bh[ni * 2 + 1][1] = t[3];
            }
            #pragma unroll
            for (int mi = 0; mi < 4; mi++)
                #pragma unroll
                for (int nj = 0; nj < 4; nj++)
                    mma_f16(acc[mi][nj], ah[mi], bh[nj]);
            // ---- A lo fragments ----
            uint32_t al[4][4];
            #pragma unroll
            for (int mi = 0; mi < 4; mi++) {
                const int row = wm * 64 + mi * 16 + (lane & 15);
                const int cl  = 4 + ks * 2 + (lane >> 4);
                ldmx4(al[mi], sb + SM_A(buf) + row * 128 + ((cl ^ (row & 7)) * 16));
            }
            #pragma unroll
            for (int mi = 0; mi < 4; mi++)
                #pragma unroll
                for (int nj = 0; nj < 4; nj++)
                    mma_f16(acc[mi][nj], al[mi], bh[nj]);
        }
        __syncthreads();
    }

    // ---- epilogue ----
    #pragma unroll
    for (int mi = 0; mi < 4; mi++) {
        const int m = m0 + wm * 64 + mi * 16 + (lane >> 2);
        #pragma unroll
        for (int nj = 0; nj < 4; nj++) {
            const int nn = n0 + wn * 32 + nj * 8 + (lane & 3) * 2;
            if (nn < HW) {
                float* o = out + (size_t)(b * COUT + m) * HW + nn;
                *(float2*)o = make_float2(acc[mi][nj][0], acc[mi][nj][1]);
                *(float2*)(o + 8 * HW) = make_float2(acc[mi][nj][2], acc[mi][nj][3]);
            }
        }
    }
}

// ---------------------------------------------------------------------------
extern "C" void kernel_launch(void* const* d_in, const int* in_sizes, int n_in,
                              void* d_out, int out_size) {
    const float* x     = (const float*)d_in[0];
    const float* convs = (const float*)d_in[1];
    const float* w1    = (const float*)d_in[2];
    const float* b1    = (const float*)d_in[3];
    const float* w2    = (const float*)d_in[4];
    const float* b2    = (const float*)d_in[5];
    float* out = (float*)d_out;

    cudaFuncSetAttribute(conv_mma, cudaFuncAttributeMaxDynamicSharedMemorySize, SM_TOTAL);

    gap_kernel<<<B_ * CIN, 256>>>(x);
    routing_kernel<<<1, 32>>>(w1, b1, w2, b2);
    shift_kernel<<<B_ * CIN, 256>>>(x);
    mix_kernel<<<dim3(COUT, B_), 128>>>(convs);
    conv_mma<<<dim3((HW + 127) / 128, COUT / 128, B_), 256, SM_TOTAL>>>(out);
}

// round 8
// speedup vs baseline: 4.4942x; 1.2832x over previous
#include <cuda_runtime.h>
#include <cuda_fp16.h>
#include <cstdint>

// Problem constants
#define B_    32
#define CIN   128
#define H_    56
#define HW    3136          // 56*56
#define COUT  256
#define KTOT  1152          // CIN*9
#define R_    16
#define KERN_PER_B (COUT*KTOT)      // 294912

// Scratch (static device arrays; no runtime allocation)
__device__ float g_gap[B_ * CIN];
__device__ float g_routing[B_ * 4];
// Mixed conv kernels, k' = r*128+ci ordering, fp16: [b][m][k']
__device__ __half g_Ah[(size_t)B_ * COUT * KTOT + 64];
// 9 shifted zero-padded fp16 copies of x: [r][b][ci][n]
#define XS_ELEMS ((size_t)9 * B_ * CIN * HW)
__device__ __half g_Xh[XS_ELEMS + 8192];

// ---------------------------------------------------------------------------
// helpers
// ---------------------------------------------------------------------------
__device__ __forceinline__ uint32_t smem_u32(const void* p) {
    uint32_t a;
    asm("{ .reg .u64 t; cvta.to.shared.u64 t, %1; cvt.u32.u64 %0, t; }"
        : "=r"(a) : "l"(p));
    return a;
}
__device__ __forceinline__ void ldmx4(uint32_t* r, uint32_t addr) {
    asm volatile("ldmatrix.sync.aligned.m8n8.x4.shared.b16 {%0,%1,%2,%3}, [%4];"
                 : "=r"(r[0]), "=r"(r[1]), "=r"(r[2]), "=r"(r[3]) : "r"(addr));
}
__device__ __forceinline__ void ldmx4t(uint32_t* r, uint32_t addr) {
    asm volatile("ldmatrix.sync.aligned.m8n8.x4.trans.shared.b16 {%0,%1,%2,%3}, [%4];"
                 : "=r"(r[0]), "=r"(r[1]), "=r"(r[2]), "=r"(r[3]) : "r"(addr));
}
__device__ __forceinline__ void mma_f16(float* d, const uint32_t* a, const uint32_t* b) {
    asm volatile(
        "mma.sync.aligned.m16n8k16.row.col.f32.f16.f16.f32 "
        "{%0,%1,%2,%3},{%4,%5,%6,%7},{%8,%9},{%0,%1,%2,%3};"
        : "+f"(d[0]), "+f"(d[1]), "+f"(d[2]), "+f"(d[3])
        : "r"(a[0]), "r"(a[1]), "r"(a[2]), "r"(a[3]), "r"(b[0]), "r"(b[1]));
}
__device__ __forceinline__ void cp16(uint32_t dst, const void* src) {
    asm volatile("cp.async.cg.shared.global [%0], [%1], 16;" :: "r"(dst), "l"(src));
}
__device__ __forceinline__ void cp_commit() {
    asm volatile("cp.async.commit_group;" ::: "memory");
}
__device__ __forceinline__ uint32_t pack_h2(__half a, __half b) {
    __half2 t = __halves2half2(a, b);
    return *reinterpret_cast<uint32_t*>(&t);
}

// ---------------------------------------------------------------------------
// 1) Global average pool
// ---------------------------------------------------------------------------
__global__ void gap_kernel(const float* __restrict__ x) {
    const int idx = blockIdx.x;
    const float* p = x + (size_t)idx * HW;
    float s = 0.f;
    for (int i = threadIdx.x; i < HW; i += 256) s += p[i];
    #pragma unroll
    for (int o = 16; o > 0; o >>= 1) s += __shfl_xor_sync(0xffffffffu, s, o);
    __shared__ float sm[8];
    if ((threadIdx.x & 31) == 0) sm[threadIdx.x >> 5] = s;
    __syncthreads();
    if (threadIdx.x < 8) {
        s = sm[threadIdx.x];
        s += __shfl_xor_sync(0xffu, s, 4);
        s += __shfl_xor_sync(0xffu, s, 2);
        s += __shfl_xor_sync(0xffu, s, 1);
        if (threadIdx.x == 0) g_gap[idx] = s * (1.0f / 3136.0f);
    }
}

// ---------------------------------------------------------------------------
// 2) Router MLP + softmax(logits/30)
// ---------------------------------------------------------------------------
__global__ void routing_kernel(const float* __restrict__ w1, const float* __restrict__ b1,
                               const float* __restrict__ w2, const float* __restrict__ b2) {
    const int b = threadIdx.x;
    if (b >= B_) return;
    float h[R_];
    #pragma unroll
    for (int r = 0; r < R_; r++) {
        float s = b1[r];
        for (int c = 0; c < CIN; c++) s += g_gap[b * CIN + c] * w1[r * CIN + c];
        h[r] = fmaxf(s, 0.f);
    }
    float lg[4];
    float mx = -1e30f;
    #pragma unroll
    for (int e = 0; e < 4; e++) {
        float s = b2[e];
        #pragma unroll
        for (int r = 0; r < R_; r++) s += h[r] * w2[e * R_ + r];
        lg[e] = s * (1.0f / 30.0f);
        mx = fmaxf(mx, lg[e]);
    }
    float den = 0.f;
    #pragma unroll
    for (int e = 0; e < 4; e++) { lg[e] = __expf(lg[e] - mx); den += lg[e]; }
    const float inv = 1.0f / den;
    #pragma unroll
    for (int e = 0; e < 4; e++) g_routing[b * 4 + e] = lg[e] * inv;
}

// ---------------------------------------------------------------------------
// 3) Shift + pad x into 9 fp16 copies: g_Xh[r][b][ci][n]
// ---------------------------------------------------------------------------
__global__ void shift_kernel(const float* __restrict__ x) {
    __shared__ float plane[HW];
    const int bc = blockIdx.x;               // b*CIN + ci
    const float* src = x + (size_t)bc * HW;
    for (int i = threadIdx.x; i < HW; i += 256) plane[i] = src[i];
    __syncthreads();
    const int b = bc >> 7, ci = bc & 127;
    for (int p = threadIdx.x; p < HW / 2; p += 256) {
        const int n0 = 2 * p;
        const int oh = n0 / H_;
        const int ow = n0 - oh * H_;         // even; ow+1 <= 55 (same row)
        #pragma unroll
        for (int r = 0; r < 9; r++) {
            const int dh = r / 3 - 1, dw = r % 3 - 1;
            const int ih = oh + dh;
            float v0 = 0.f, v1 = 0.f;
            if ((unsigned)ih < (unsigned)H_) {
                const int iw0 = ow + dw;
                if ((unsigned)iw0 < (unsigned)H_) v0 = plane[ih * H_ + iw0];
                const int iw1 = iw0 + 1;
                if ((unsigned)iw1 < (unsigned)H_) v1 = plane[ih * H_ + iw1];
            }
            const size_t off = ((size_t)(r * B_ + b) * CIN + ci) * (HW / 2) + p;
            ((uint32_t*)g_Xh)[off] = pack_h2(__float2half_rn(v0), __float2half_rn(v1));
        }
    }
}

// ---------------------------------------------------------------------------
// 4) Mix expert kernels -> g_Ah[b][m][k'] with k' = r*128+ci, fp16
// ---------------------------------------------------------------------------
__global__ void mix_kernel(const float* __restrict__ convs) {
    const int m = blockIdx.x;
    const int b = blockIdx.y;
    const float r0 = g_routing[b * 4 + 0];
    const float r1 = g_routing[b * 4 + 1];
    const float r2 = g_routing[b * 4 + 2];
    const float r3 = g_routing[b * 4 + 3];
    for (int p = threadIdx.x; p < KTOT / 2; p += 128) {   // p -> k' pair (2*p, 2*p+1)
        const int r = p >> 6;
        const int ci = (p & 63) * 2;
        const int base = m * KTOT + ci * 9 + r;
        const float* c0 = convs + base;
        float v0 = r0 * c0[0] + r1 * c0[KERN_PER_B] + r2 * c0[2 * KERN_PER_B] + r3 * c0[3 * KERN_PER_B];
        const float* c1 = convs + base + 9;
        float v1 = r0 * c1[0] + r1 * c1[KERN_PER_B] + r2 * c1[2 * KERN_PER_B] + r3 * c1[3 * KERN_PER_B];
        const size_t off = (size_t)(b * COUT + m) * (KTOT / 2) + p;
        ((uint32_t*)g_Ah)[off] = pack_h2(__float2half_rn(v0), __float2half_rn(v1));
    }
}

// ---------------------------------------------------------------------------
// 5) Per-sample GEMM on mma.sync (single-pass fp16), cp.async double buffer.
//    CTA tile 128m x 128n, BK=32 (36 stages), 8 warps -> warp tile 64m x 32n.
//    smem: A[2][128 rows][128B; chunks 0..3 at slot c^(row&7)]
//          B[2][32 krows x 256B, XOR swizzle]
// ---------------------------------------------------------------------------
#define STG    24576                 // A 16K + B 8K per stage
#define SM_A(buf)  ((buf) * STG)
#define SM_B(buf)  ((buf) * STG + 16384)
#define SM_TOTAL   (2 * STG)

__global__ void __launch_bounds__(256, 2)
conv_mma(float* __restrict__ out) {
    extern __shared__ __align__(128) char smem[];
    const uint32_t sb = smem_u32(smem);

    const int tid  = threadIdx.x;
    const int wid  = tid >> 5;
    const int lane = tid & 31;
    const int wm   = wid & 1;          // 2 warps along m
    const int wn   = wid >> 1;         // 4 warps along n

    const int b  = blockIdx.z;
    const int m0 = blockIdx.y * 128;
    const int n0 = blockIdx.x * 128;

    float acc[4][4][4];
    #pragma unroll
    for (int i = 0; i < 4; i++)
        #pragma unroll
        for (int j = 0; j < 4; j++)
            #pragma unroll
            for (int q = 0; q < 4; q++) acc[i][j][q] = 0.f;

    // ---- stage loader (A: 512 cp16, B: 512 cp16 across 256 threads) ----
    auto load_stage = [&](int s, int buf) {
        const int r   = s >> 2;
        const int ci0 = (s & 3) * 32;
        // A: row m 0..127, chunk c 0..3
        #pragma unroll
        for (int q = 0; q < 2; q++) {
            const int id  = q * 256 + tid;
            const int row = id >> 2;
            const int c   = id & 3;
            const __half* src =
                g_Ah + (size_t)(b * COUT + m0 + row) * KTOT + s * 32 + c * 8;
            cp16(sb + SM_A(buf) + row * 128 + ((c ^ (row & 7)) * 16), src);
        }
        // B: krow 0..31, chunk c 0..15
        #pragma unroll
        for (int q = 0; q < 2; q++) {
            const int id = q * 256 + tid;
            const int kr = id >> 4;
            const int c  = id & 15;
            const __half* src =
                g_Xh + (size_t)((r * B_ + b) * CIN + ci0 + kr) * HW + n0 + c * 8;
            cp16(sb + SM_B(buf) + kr * 256 + ((c ^ (kr & 7)) * 16), src);
        }
        cp_commit();
    };

    load_stage(0, 0);

    for (int s = 0; s < 36; s++) {
        const int buf = s & 1;
        if (s + 1 < 36) {
            load_stage(s + 1, buf ^ 1);
            asm volatile("cp.async.wait_group 1;" ::: "memory");
        } else {
            asm volatile("cp.async.wait_group 0;" ::: "memory");
        }
        __syncthreads();

        #pragma unroll
        for (int ks = 0; ks < 2; ks++) {
            // ---- A fragments ----
            uint32_t ah[4][4];
            #pragma unroll
            for (int mi = 0; mi < 4; mi++) {
                const int row = wm * 64 + mi * 16 + (lane & 15);
                const int cl  = ks * 2 + (lane >> 4);
                ldmx4(ah[mi], sb + SM_A(buf) + row * 128 + ((cl ^ (row & 7)) * 16));
            }
            // ---- B fragments (ldmatrix.trans from k-major) ----
            uint32_t bh[4][2];
            #pragma unroll
            for (int ni = 0; ni < 2; ni++) {
                const int mat = lane >> 3, j = lane & 7;
                const int kr  = ks * 16 + (mat & 1) * 8 + j;
                const int nc  = wn * 4 + ni * 2 + (mat >> 1);
                uint32_t t[4];
                ldmx4t(t, sb + SM_B(buf) + kr * 256 + ((nc ^ (kr & 7)) * 16));
                bh[ni * 2 + 0][0] = t[0]; bh[ni * 2 + 0][1] = t[1];
                bh[ni * 2 + 1][0] = t[2]; bh[ni * 2 + 1][1] = t[3];
            }
            #pragma unroll
            for (int mi = 0; mi < 4; mi++)
                #pragma unroll
                for (int nj = 0; nj < 4; nj++)
                    mma_f16(acc[mi][nj], ah[mi], bh[nj]);
        }
        __syncthreads();
    }

    // ---- epilogue ----
    #pragma unroll
    for (int mi = 0; mi < 4; mi++) {
        const int m = m0 + wm * 64 + mi * 16 + (lane >> 2);
        #pragma unroll
        for (int nj = 0; nj < 4; nj++) {
            const int nn = n0 + wn * 32 + nj * 8 + (lane & 3) * 2;
            if (nn < HW) {
                float* o = out + (size_t)(b * COUT + m) * HW + nn;
                *(float2*)o = make_float2(acc[mi][nj][0], acc[mi][nj][1]);
                *(float2*)(o + 8 * HW) = make_float2(acc[mi][nj][2], acc[mi][nj][3]);
            }
        }
    }
}

// ---------------------------------------------------------------------------
extern "C" void kernel_launch(void* const* d_in, const int* in_sizes, int n_in,
                              void* d_out, int out_size) {
    const float* x     = (const float*)d_in[0];
    const float* convs = (const float*)d_in[1];
    const float* w1    = (const float*)d_in[2];
    const float* b1    = (const float*)d_in[3];
    const float* w2    = (const float*)d_in[4];
    const float* b2    = (const float*)d_in[5];
    float* out = (float*)d_out;

    cudaFuncSetAttribute(conv_mma, cudaFuncAttributeMaxDynamicSharedMemorySize, SM_TOTAL);

    gap_kernel<<<B_ * CIN, 256>>>(x);
    routing_kernel<<<1, 32>>>(w1, b1, w2, b2);
    shift_kernel<<<B_ * CIN, 256>>>(x);
    mix_kernel<<<dim3(COUT, B_), 128>>>(convs);
    conv_mma<<<dim3((HW + 127) / 128, COUT / 128, B_), 256, SM_TOTAL>>>(out);
}